// round 15
// baseline (speedup 1.0000x reference)
#include <cuda_runtime.h>
#include <cuda_fp16.h>
#include <math.h>
#include <stdint.h>

// Problem constants
constexpr int Bc = 4;
constexpr int Sc = 2048;
constexpr int Dc = 1024;
constexpr int Hc = 16;
constexpr int DHc = 64;
constexpr int Mc = Bc * Sc;    // 8192

// Scratch (device globals — no allocation allowed)
__device__ __align__(16) __half g_q[(size_t)Bc * Hc * Sc * DHc];
__device__ __align__(16) __half g_k[(size_t)Bc * Hc * Sc * DHc];
__device__ __align__(16) __half g_v[(size_t)Bc * Hc * Sc * DHc];
__device__ __align__(16) __half g_ctx[(size_t)Mc * Dc];
__device__ __align__(16) __half g_xh[(size_t)Mc * Dc];          // x in fp16
__device__ __align__(16) __half g_wcat[(size_t)Dc * 3 * Dc];    // [k][3072] = Wq|Wk|Wv
__device__ __align__(16) __half g_woh[(size_t)Dc * Dc];         // Wo fp16

// ---- primitives ------------------------------------------------------------
__device__ __forceinline__ void mma16h(float* c, const uint32_t* a, const uint32_t* b) {
    asm volatile(
        "mma.sync.aligned.m16n8k16.row.col.f32.f16.f16.f32 "
        "{%0,%1,%2,%3}, {%4,%5,%6,%7}, {%8,%9}, {%0,%1,%2,%3};\n"
        : "+f"(c[0]), "+f"(c[1]), "+f"(c[2]), "+f"(c[3])
        : "r"(a[0]), "r"(a[1]), "r"(a[2]), "r"(a[3]), "r"(b[0]), "r"(b[1]));
}
__device__ __forceinline__ void ldsm_x4(uint32_t* r, uint32_t addr) {
    asm volatile("ldmatrix.sync.aligned.m8n8.x4.shared.b16 {%0,%1,%2,%3}, [%4];"
                 : "=r"(r[0]), "=r"(r[1]), "=r"(r[2]), "=r"(r[3]) : "r"(addr));
}
__device__ __forceinline__ void ldsm_x4t(uint32_t* r, uint32_t addr) {
    asm volatile("ldmatrix.sync.aligned.m8n8.x4.trans.shared.b16 {%0,%1,%2,%3}, [%4];"
                 : "=r"(r[0]), "=r"(r[1]), "=r"(r[2]), "=r"(r[3]) : "r"(addr));
}
__device__ __forceinline__ uint32_t exp2_f16x2(float lo, float hi) {
    uint32_t u;
    asm("{\n\t.reg .b32 t;\n\t"
        "cvt.rn.f16x2.f32 t, %1, %2;\n\t"
        "ex2.approx.f16x2 %0, t;\n\t}"
        : "=r"(u) : "f"(hi), "f"(lo));
    return u;
}
__device__ __forceinline__ void cp16(uint32_t saddr, const void* g) {
    asm volatile("cp.async.cg.shared.global [%0], [%1], 16;" :: "r"(saddr), "l"(g));
}
__device__ __forceinline__ void cp_commit() { asm volatile("cp.async.commit_group;" ::: "memory"); }
__device__ __forceinline__ void cp_wait0()  { asm volatile("cp.async.wait_group 0;" ::: "memory"); }

// ---------------------------------------------------------------------------
// fp32 -> fp16 conversion pre-pass (single fused kernel: x + all weights)
// ---------------------------------------------------------------------------
__global__ __launch_bounds__(256) void cvt_all(
    const float* __restrict__ x,
    const float* __restrict__ wq, const float* __restrict__ wk,
    const float* __restrict__ wv, const float* __restrict__ wo)
{
    if (blockIdx.x < 4096) {
        const size_t i = ((size_t)blockIdx.x * 256 + threadIdx.x) * 8;
        const float4 f0 = *(const float4*)(x + i);
        const float4 f1 = *(const float4*)(x + i + 4);
        __half2 h0 = __floats2half2_rn(f0.x, f0.y), h1 = __floats2half2_rn(f0.z, f0.w);
        __half2 h2 = __floats2half2_rn(f1.x, f1.y), h3 = __floats2half2_rn(f1.z, f1.w);
        uint4 p = { *(uint32_t*)&h0, *(uint32_t*)&h1, *(uint32_t*)&h2, *(uint32_t*)&h3 };
        *(uint4*)(g_xh + i) = p;
    } else {
        const size_t i = ((size_t)(blockIdx.x - 4096) * 256 + threadIdx.x) * 4;
        const int k = (int)(i >> 10), n = (int)(i & 1023);
        const float4 q4 = *(const float4*)(wq + i);
        const float4 k4 = *(const float4*)(wk + i);
        const float4 v4 = *(const float4*)(wv + i);
        const float4 o4 = *(const float4*)(wo + i);
        __half2 a, b;
        a = __floats2half2_rn(q4.x, q4.y); b = __floats2half2_rn(q4.z, q4.w);
        { uint2 p = { *(uint32_t*)&a, *(uint32_t*)&b }; *(uint2*)(g_wcat + (size_t)k * 3072 + n) = p; }
        a = __floats2half2_rn(k4.x, k4.y); b = __floats2half2_rn(k4.z, k4.w);
        { uint2 p = { *(uint32_t*)&a, *(uint32_t*)&b }; *(uint2*)(g_wcat + (size_t)k * 3072 + 1024 + n) = p; }
        a = __floats2half2_rn(v4.x, v4.y); b = __floats2half2_rn(v4.z, v4.w);
        { uint2 p = { *(uint32_t*)&a, *(uint32_t*)&b }; *(uint2*)(g_wcat + (size_t)k * 3072 + 2048 + n) = p; }
        a = __floats2half2_rn(o4.x, o4.y); b = __floats2half2_rn(o4.z, o4.w);
        { uint2 p = { *(uint32_t*)&a, *(uint32_t*)&b }; *(uint2*)(g_woh + i) = p; }
    }
}

// ---------------------------------------------------------------------------
// FP16 GEMM, small-CTA + pair pipeline: tile 64x128, BK=32, 128 threads
//   (4 warps, warp tile 64x32), 4 CTAs/SM, 4 stages, TWO K-iters per
//   sync/wait (one cp group per pair).
// ---------------------------------------------------------------------------
constexpr int G_NSTG = 4;
constexpr int GA_PITCH = 40;                       // halves (80 B)
constexpr int GB_PITCH = 136;                      // halves (272 B)
constexpr uint32_t GA_STG = 64 * GA_PITCH * 2;     // 5120 B
constexpr uint32_t GB_STG = 32 * GB_PITCH * 2;     // 8704 B
constexpr uint32_t GB_OFF = G_NSTG * GA_STG;       // 20480
constexpr int G_SMEM = (int)(GB_OFF + G_NSTG * GB_STG); // 55296 B -> 4 CTAs = 221 KB
constexpr int G_NIT = Dc / 32;                     // 32

template<bool QKV>
__global__ __launch_bounds__(128, 4) void gemm_cp(
    const float* __restrict__ bias0,
    const float* __restrict__ bias1,
    const float* __restrict__ bias2,
    float* __restrict__ outF,
    float qscale)
{
    extern __shared__ char gsm[];
    const uint32_t sbase = (uint32_t)__cvta_generic_to_shared(gsm);
    constexpr int LDW = QKV ? 3072 : 1024;
    const __half* A = QKV ? g_xh : g_ctx;
    const __half* W = QKV ? g_wcat : g_woh;

    const int tid = threadIdx.x, lane = tid & 31, wid = tid >> 5;
    const int wn = wid;
    const int m0 = blockIdx.y * 64;
    const int n0 = blockIdx.x * 128;
    const int rq = lane >> 2, qd = lane & 3;

    const int rA = tid >> 1, cA = (tid & 1) * 16;
    const int rB = tid >> 4, cB = (tid & 15) * 8;
    const __half* aSrc = A + (size_t)(m0 + rA) * Dc + cA;
    const __half* bSrc = W + (size_t)rB * LDW + n0 + cB;

    auto fill = [&](int j) {
        const int s = j & (G_NSTG - 1);
        const int k0 = j * 32;
        const uint32_t aS = sbase + s * GA_STG;
        const uint32_t bS = sbase + GB_OFF + s * GB_STG;
        cp16(aS + (rA * GA_PITCH + cA) * 2,     aSrc + k0);
        cp16(aS + (rA * GA_PITCH + cA + 8) * 2, aSrc + k0 + 8);
        const __half* bG = bSrc + (size_t)k0 * LDW;
        cp16(bS + (rB * GB_PITCH + cB) * 2,        bG);
        cp16(bS + ((rB + 8) * GB_PITCH + cB) * 2,  bG + (size_t)8 * LDW);
        cp16(bS + ((rB + 16) * GB_PITCH + cB) * 2, bG + (size_t)16 * LDW);
        cp16(bS + ((rB + 24) * GB_PITCH + cB) * 2, bG + (size_t)24 * LDW);
    };

    const uint32_t a_frag = sbase + ((lane & 15) * GA_PITCH + (lane >> 4) * 8) * 2;
    const uint32_t b_frag = sbase + GB_OFF + ((lane & 15) * GB_PITCH + wn * 32 + (lane >> 4) * 8) * 2;

    float acc[4][4][4] = {};

    auto compute = [&](int it) {
        const int s = it & (G_NSTG - 1);
        const uint32_t aS = a_frag + s * GA_STG;
        const uint32_t bS = b_frag + s * GB_STG;
        #pragma unroll
        for (int kk = 0; kk < 2; ++kk) {
            uint32_t aF[4][4];
            #pragma unroll
            for (int mf = 0; mf < 4; ++mf)
                ldsm_x4(aF[mf], aS + (mf * 16 * GA_PITCH + kk * 16) * 2);
            #pragma unroll
            for (int ng = 0; ng < 2; ++ng) {
                uint32_t bF[4];
                ldsm_x4t(bF, bS + (kk * 16 * GB_PITCH + ng * 16) * 2);
                #pragma unroll
                for (int s2 = 0; s2 < 2; ++s2) {
                    const int nf = ng * 2 + s2;
                    #pragma unroll
                    for (int mf = 0; mf < 4; ++mf)
                        mma16h(acc[mf][nf], aF[mf], &bF[s2 * 2]);
                }
            }
        }
    };

    fill(0); fill(1); cp_commit();

    for (int it = 0; it < G_NIT; it += 2) {
        cp_wait0();
        __syncthreads();
        if (it + 2 < G_NIT) { fill(it + 2); fill(it + 3); cp_commit(); }
        compute(it);
        compute(it + 1);
    }

    // Epilogue
    if constexpr (QKV) {
        const int wsel = blockIdx.x >> 3;
        const int nl0 = (blockIdx.x & 7) * 128;
        __half* outp = wsel == 0 ? g_q : wsel == 1 ? g_k : g_v;
        const float* bp = wsel == 0 ? bias0 : wsel == 1 ? bias1 : bias2;
        const float scale = wsel == 0 ? qscale : 1.0f;
        #pragma unroll
        for (int nf = 0; nf < 4; ++nf) {
            const int ncol = nl0 + wn * 32 + nf * 8 + 2 * qd;
            const float bx = bp[ncol], by = bp[ncol + 1];
            const int h = ncol >> 6, d = ncol & 63;
            #pragma unroll
            for (int mf = 0; mf < 4; ++mf) {
                const int r = m0 + mf * 16 + rq;
                __half2 p0 = __floats2half2_rn((acc[mf][nf][0] + bx) * scale,
                                               (acc[mf][nf][1] + by) * scale);
                __half2 p1 = __floats2half2_rn((acc[mf][nf][2] + bx) * scale,
                                               (acc[mf][nf][3] + by) * scale);
                const int bb0 = r >> 11, ss0 = r & 2047;
                const int bb1 = (r + 8) >> 11, ss1 = (r + 8) & 2047;
                *(__half2*)(outp + (((size_t)(bb0 * Hc + h) * Sc + ss0) * DHc + d)) = p0;
                *(__half2*)(outp + (((size_t)(bb1 * Hc + h) * Sc + ss1) * DHc + d)) = p1;
            }
        }
    } else {
        #pragma unroll
        for (int nf = 0; nf < 4; ++nf) {
            const int col = n0 + wn * 32 + nf * 8 + 2 * qd;
            const float bx = bias0[col], by = bias0[col + 1];
            #pragma unroll
            for (int mf = 0; mf < 4; ++mf) {
                const int r = m0 + mf * 16 + rq;
                *(float2*)(outF + (size_t)r * Dc + col) =
                    make_float2(acc[mf][nf][0] + bx, acc[mf][nf][1] + by);
                *(float2*)(outF + (size_t)(r + 8) * Dc + col) =
                    make_float2(acc[mf][nf][2] + bx, acc[mf][nf][3] + by);
            }
        }
    }
}

// ---------------------------------------------------------------------------
// FP16 flash attention: MAX-FREE softmax, pair pipeline (4 stages, 2 tiles
// per sync), li accumulated in registers from aP (no ones-column mma).
//   Grid (S/128, B*H), 256 thr = 8 warps x 16 q-rows. Key tile 64.
// ---------------------------------------------------------------------------
constexpr int F_NSTG = 4;
constexpr int F_STG  = 64 * 72;                   // halves per stage
constexpr int F_K_OFF = 128 * 72;                 // after Q
constexpr int F_V_OFF = F_K_OFF + F_NSTG * F_STG;
constexpr int FLASH_SMEM = (F_V_OFF + F_NSTG * F_STG) * 2;   // 92160 B -> 2 CTAs
constexpr int F_NT = Sc / 64;                     // 32

__global__ __launch_bounds__(256, 2) void flash_h()
{
    extern __shared__ __half dsm[];
    const int tid = threadIdx.x, lane = tid & 31, wid = tid >> 5;
    const int qt = blockIdx.x, bh = blockIdx.y;
    const __half* Q = g_q + (size_t)bh * Sc * DHc;
    const __half* K = g_k + (size_t)bh * Sc * DHc;
    const __half* V = g_v + (size_t)bh * Sc * DHc;
    const int rq = lane >> 2, qd = lane & 3;

    const uint32_t base = (uint32_t)__cvta_generic_to_shared(dsm);
    const uint32_t k_base = base + F_K_OFF * 2;
    const uint32_t v_base = base + F_V_OFF * 2;

    // Q tile (128 x 64 halves)
    __half (*Qs)[72] = (__half(*)[72])dsm;
    #pragma unroll
    for (int j = 0; j < 4; ++j) {
        const int i = tid + j * 256;
        const int r = i >> 3, c = (i & 7) * 8;
        *(uint4*)&Qs[r][c] = *(const uint4*)(Q + (size_t)(qt * 128 + r) * DHc + c);
    }

    // cp.async K/V mapping (2 x 16B per array per thread)
    const int rKV = tid >> 3, cKV = (tid & 7) * 8;
    auto fillKV = [&](int t) {
        const uint32_t so = (uint32_t)(t & (F_NSTG - 1)) * F_STG * 2;
        const size_t go = (size_t)t * 64 * DHc;
        cp16(k_base + so + (rKV * 72 + cKV) * 2,        K + go + (size_t)rKV * DHc + cKV);
        cp16(k_base + so + ((rKV + 32) * 72 + cKV) * 2, K + go + (size_t)(rKV + 32) * DHc + cKV);
        cp16(v_base + so + (rKV * 72 + cKV) * 2,        V + go + (size_t)rKV * DHc + cKV);
        cp16(v_base + so + ((rKV + 32) * 72 + cKV) * 2, V + go + (size_t)(rKV + 32) * DHc + cKV);
    };

    fillKV(0); fillKV(1); cp_commit();
    __syncthreads();    // Q visible

    // Q fragments in registers for the whole loop
    uint32_t aQ[4][4];
    {
        const uint32_t qa = base + ((wid * 16 + (lane & 15)) * 72 + (lane >> 4) * 8) * 2;
        #pragma unroll
        for (int kk = 0; kk < 4; ++kk)
            ldsm_x4(aQ[kk], qa + kk * 16 * 2);
    }

    float accO[8][4] = {};
    float li[2] = {0.0f, 0.0f};

    const uint32_t k_frag = k_base + (((lane >> 4) * 8 + (lane & 7)) * 72 + ((lane >> 3) & 1) * 8) * 2;
    const uint32_t v_frag = v_base + ((lane & 15) * 72 + (lane >> 4) * 8) * 2;

    auto process = [&](int t) {
        const uint32_t so = (uint32_t)(t & (F_NSTG - 1)) * F_STG * 2;

        // S = Q K^T  (log2-unit scores: Q pre-scaled by log2e/8)
        float accS[8][4] = {};
        #pragma unroll
        for (int kk = 0; kk < 4; ++kk) {
            #pragma unroll
            for (int ng = 0; ng < 4; ++ng) {
                uint32_t bK[4];
                ldsm_x4(bK, k_frag + so + (ng * 16 * 72 + kk * 16) * 2);
                mma16h(accS[2 * ng],     aQ[kk], &bK[0]);
                mma16h(accS[2 * ng + 1], aQ[kk], &bK[2]);
            }
        }

        // Max-free softmax: P = exp2(S) into mma A-fragments
        uint32_t aP[4][4];
        #pragma unroll
        for (int nf = 0; nf < 8; ++nf) {
            aP[nf >> 1][((nf & 1) << 1) | 0] = exp2_f16x2(accS[nf][0], accS[nf][1]);
            aP[nf >> 1][((nf & 1) << 1) | 1] = exp2_f16x2(accS[nf][2], accS[nf][3]);
        }

        // li += row-partials (fp32, on idle fma pipe; quad-reduce at epilogue)
        #pragma unroll
        for (int h = 0; h < 2; ++h) {
            float s = 0.0f;
            #pragma unroll
            for (int nf = 0; nf < 8; ++nf) {
                const float2 f = __half22float2(
                    *(const __half2*)&aP[nf >> 1][((nf & 1) << 1) | h]);
                s += f.x + f.y;
            }
            li[h] += s;
        }

        // O += P @ V
        #pragma unroll
        for (int kk = 0; kk < 4; ++kk) {
            #pragma unroll
            for (int dg = 0; dg < 4; ++dg) {
                uint32_t bV[4];
                ldsm_x4t(bV, v_frag + so + (kk * 16 * 72 + dg * 16) * 2);
                mma16h(accO[2 * dg],     aP[kk], &bV[0]);
                mma16h(accO[2 * dg + 1], aP[kk], &bV[2]);
            }
        }
    };

    for (int t = 0; t < F_NT; t += 2) {
        cp_wait0();
        __syncthreads();
        if (t + 2 < F_NT) { fillKV(t + 2); fillKV(t + 3); cp_commit(); }
        process(t);
        process(t + 1);
    }

    // Epilogue: quad-reduce li, normalize, write ctx [B,S,D]
    #pragma unroll
    for (int h = 0; h < 2; ++h) {
        li[h] += __shfl_xor_sync(0xffffffffu, li[h], 1);
        li[h] += __shfl_xor_sync(0xffffffffu, li[h], 2);
    }
    const float inv0 = 1.0f / li[0];
    const float inv1 = 1.0f / li[1];

    const int bb = bh >> 4, hh = bh & 15;
    const int row = wid * 16 + rq;
    #pragma unroll
    for (int h = 0; h < 2; ++h) {
        const int s_idx = qt * 128 + row + 8 * h;
        const float inv = h ? inv1 : inv0;
        #pragma unroll
        for (int nf = 0; nf < 8; ++nf) {
            __half2 o = __floats2half2_rn(accO[nf][2 * h] * inv,
                                          accO[nf][2 * h + 1] * inv);
            *(__half2*)(g_ctx + ((size_t)(bb * Sc + s_idx) * Dc + hh * DHc + nf * 8 + 2 * qd)) = o;
        }
    }
}

// ---------------------------------------------------------------------------
extern "C" void kernel_launch(void* const* d_in, const int* in_sizes, int n_in,
                              void* d_out, int out_size)
{
    const float* x  = (const float*)d_in[0];
    const float* wq = (const float*)d_in[1];
    const float* bq = (const float*)d_in[2];
    const float* wk = (const float*)d_in[3];
    const float* bk = (const float*)d_in[4];
    const float* wv = (const float*)d_in[5];
    const float* bv = (const float*)d_in[6];
    const float* wo = (const float*)d_in[7];
    const float* bo = (const float*)d_in[8];
    float* out = (float*)d_out;

    static bool attr_set = false;
    if (!attr_set) {
        cudaFuncSetAttribute(flash_h, cudaFuncAttributeMaxDynamicSharedMemorySize,
                             FLASH_SMEM);
        cudaFuncSetAttribute(gemm_cp<true>, cudaFuncAttributeMaxDynamicSharedMemorySize,
                             G_SMEM);
        cudaFuncSetAttribute(gemm_cp<false>, cudaFuncAttributeMaxDynamicSharedMemorySize,
                             G_SMEM);
        attr_set = true;
    }

    const float qscale = 1.4426950408889634f / 8.0f;   // log2(e)/sqrt(Dh)

    // fp32 -> fp16 conversion pre-pass (fused single launch)
    cvt_all<<<5120, 256>>>(x, wq, wk, wv, wo);

    // Fused QKV projection (N = 3072), 64x128 tiles, 128 thr, 4 CTAs/SM
    gemm_cp<true><<<dim3(3 * Dc / 128, Mc / 64), 128, G_SMEM>>>(bq, bk, bv, nullptr, qscale);

    // Attention (max-free softmax, pair pipeline)
    flash_h<<<dim3(Sc / 128, Bc * Hc), 256, FLASH_SMEM>>>();

    // Output projection
    gemm_cp<false><<<dim3(Dc / 128, Mc / 64), 128, G_SMEM>>>(bo, nullptr, nullptr, out, 1.0f);
}

// round 16
// speedup vs baseline: 1.0011x; 1.0011x over previous
#include <cuda_runtime.h>
#include <cuda_fp16.h>
#include <math.h>
#include <stdint.h>

// Problem constants
constexpr int Bc = 4;
constexpr int Sc = 2048;
constexpr int Dc = 1024;
constexpr int Hc = 16;
constexpr int DHc = 64;
constexpr int Mc = Bc * Sc;    // 8192

// Scratch (device globals — no allocation allowed)
__device__ __align__(16) __half g_q[(size_t)Bc * Hc * Sc * DHc];
__device__ __align__(16) __half g_k[(size_t)Bc * Hc * Sc * DHc];
__device__ __align__(16) __half g_v[(size_t)Bc * Hc * Sc * DHc];
__device__ __align__(16) __half g_ctx[(size_t)Mc * Dc];
__device__ __align__(16) __half g_xh[(size_t)Mc * Dc];          // x in fp16
__device__ __align__(16) __half g_wcat[(size_t)Dc * 3 * Dc];    // [k][3072] = Wq|Wk|Wv
__device__ __align__(16) __half g_woh[(size_t)Dc * Dc];         // Wo fp16

// ---- primitives ------------------------------------------------------------
__device__ __forceinline__ void mma16h(float* c, const uint32_t* a, const uint32_t* b) {
    asm volatile(
        "mma.sync.aligned.m16n8k16.row.col.f32.f16.f16.f32 "
        "{%0,%1,%2,%3}, {%4,%5,%6,%7}, {%8,%9}, {%0,%1,%2,%3};\n"
        : "+f"(c[0]), "+f"(c[1]), "+f"(c[2]), "+f"(c[3])
        : "r"(a[0]), "r"(a[1]), "r"(a[2]), "r"(a[3]), "r"(b[0]), "r"(b[1]));
}
__device__ __forceinline__ void ldsm_x4(uint32_t* r, uint32_t addr) {
    asm volatile("ldmatrix.sync.aligned.m8n8.x4.shared.b16 {%0,%1,%2,%3}, [%4];"
                 : "=r"(r[0]), "=r"(r[1]), "=r"(r[2]), "=r"(r[3]) : "r"(addr));
}
__device__ __forceinline__ void ldsm_x4t(uint32_t* r, uint32_t addr) {
    asm volatile("ldmatrix.sync.aligned.m8n8.x4.trans.shared.b16 {%0,%1,%2,%3}, [%4];"
                 : "=r"(r[0]), "=r"(r[1]), "=r"(r[2]), "=r"(r[3]) : "r"(addr));
}
__device__ __forceinline__ uint32_t exp2_f16x2(float lo, float hi) {
    uint32_t u;
    asm("{\n\t.reg .b32 t;\n\t"
        "cvt.rn.f16x2.f32 t, %1, %2;\n\t"
        "ex2.approx.f16x2 %0, t;\n\t}"
        : "=r"(u) : "f"(hi), "f"(lo));
    return u;
}
__device__ __forceinline__ void cp16(uint32_t saddr, const void* g) {
    asm volatile("cp.async.cg.shared.global [%0], [%1], 16;" :: "r"(saddr), "l"(g));
}
__device__ __forceinline__ void cp_commit() { asm volatile("cp.async.commit_group;" ::: "memory"); }
__device__ __forceinline__ void cp_wait1()  { asm volatile("cp.async.wait_group 1;" ::: "memory"); }
__device__ __forceinline__ void cp_wait0()  { asm volatile("cp.async.wait_group 0;" ::: "memory"); }

// ---------------------------------------------------------------------------
// fp32 -> fp16 conversion pre-pass (single fused kernel: x + all weights)
// ---------------------------------------------------------------------------
__global__ __launch_bounds__(256) void cvt_all(
    const float* __restrict__ x,
    const float* __restrict__ wq, const float* __restrict__ wk,
    const float* __restrict__ wv, const float* __restrict__ wo)
{
    if (blockIdx.x < 4096) {
        const size_t i = ((size_t)blockIdx.x * 256 + threadIdx.x) * 8;
        const float4 f0 = *(const float4*)(x + i);
        const float4 f1 = *(const float4*)(x + i + 4);
        __half2 h0 = __floats2half2_rn(f0.x, f0.y), h1 = __floats2half2_rn(f0.z, f0.w);
        __half2 h2 = __floats2half2_rn(f1.x, f1.y), h3 = __floats2half2_rn(f1.z, f1.w);
        uint4 p = { *(uint32_t*)&h0, *(uint32_t*)&h1, *(uint32_t*)&h2, *(uint32_t*)&h3 };
        *(uint4*)(g_xh + i) = p;
    } else {
        const size_t i = ((size_t)(blockIdx.x - 4096) * 256 + threadIdx.x) * 4;
        const int k = (int)(i >> 10), n = (int)(i & 1023);
        const float4 q4 = *(const float4*)(wq + i);
        const float4 k4 = *(const float4*)(wk + i);
        const float4 v4 = *(const float4*)(wv + i);
        const float4 o4 = *(const float4*)(wo + i);
        __half2 a, b;
        a = __floats2half2_rn(q4.x, q4.y); b = __floats2half2_rn(q4.z, q4.w);
        { uint2 p = { *(uint32_t*)&a, *(uint32_t*)&b }; *(uint2*)(g_wcat + (size_t)k * 3072 + n) = p; }
        a = __floats2half2_rn(k4.x, k4.y); b = __floats2half2_rn(k4.z, k4.w);
        { uint2 p = { *(uint32_t*)&a, *(uint32_t*)&b }; *(uint2*)(g_wcat + (size_t)k * 3072 + 1024 + n) = p; }
        a = __floats2half2_rn(v4.x, v4.y); b = __floats2half2_rn(v4.z, v4.w);
        { uint2 p = { *(uint32_t*)&a, *(uint32_t*)&b }; *(uint2*)(g_wcat + (size_t)k * 3072 + 2048 + n) = p; }
        a = __floats2half2_rn(o4.x, o4.y); b = __floats2half2_rn(o4.z, o4.w);
        { uint2 p = { *(uint32_t*)&a, *(uint32_t*)&b }; *(uint2*)(g_woh + i) = p; }
    }
}

// ---------------------------------------------------------------------------
// FP16 GEMM (R14 proven config): tile 64x128, BK=32, 128 threads (4 warps,
//   warp tile 64x32), 3-stage cp.async, one sync per iter, 4 CTAs/SM.
//   QKV=true:  A=g_xh, W=g_wcat (ld 3072), out -> g_q/g_k/g_v head-major fp16.
//   QKV=false: A=g_ctx, W=g_woh (ld 1024), out -> float [M,1024] (d_out).
// ---------------------------------------------------------------------------
constexpr int GA_PITCH = 40;                       // halves (80 B)
constexpr int GB_PITCH = 136;                      // halves (272 B)
constexpr uint32_t GA_STG = 64 * GA_PITCH * 2;     // 5120 B
constexpr uint32_t GB_STG = 32 * GB_PITCH * 2;     // 8704 B
constexpr uint32_t GB_OFF = 3 * GA_STG;            // 15360
constexpr int G_SMEM = (int)(GB_OFF + 3 * GB_STG); // 41472 B -> 4 CTAs = 166 KB
constexpr int G_NIT = Dc / 32;                     // 32

template<bool QKV>
__global__ __launch_bounds__(128, 4) void gemm_cp(
    const float* __restrict__ bias0,
    const float* __restrict__ bias1,
    const float* __restrict__ bias2,
    float* __restrict__ outF,
    float qscale)
{
    extern __shared__ char gsm[];
    const uint32_t sbase = (uint32_t)__cvta_generic_to_shared(gsm);
    constexpr int LDW = QKV ? 3072 : 1024;
    const __half* A = QKV ? g_xh : g_ctx;
    const __half* W = QKV ? g_wcat : g_woh;

    const int tid = threadIdx.x, lane = tid & 31, wid = tid >> 5;
    const int wn = wid;                         // 4 warps across N
    const int m0 = blockIdx.y * 64;
    const int n0 = blockIdx.x * 128;
    const int rq = lane >> 2, qd = lane & 3;

    // cp.async mapping per stage: A 2 chunks + B 4 chunks per thread (16B each)
    const int rA = tid >> 1, cA = (tid & 1) * 16;       // rows 0..63, cols {0,16}+8
    const int rB = tid >> 4, cB = (tid & 15) * 8;       // rows 0..7 (+8,+16,+24)
    const __half* aSrc = A + (size_t)(m0 + rA) * Dc + cA;
    const __half* bSrc = W + (size_t)rB * LDW + n0 + cB;

    auto fill = [&](int j) {
        const int s = j % 3;
        const int k0 = j * 32;
        const uint32_t aS = sbase + s * GA_STG;
        const uint32_t bS = sbase + GB_OFF + s * GB_STG;
        cp16(aS + (rA * GA_PITCH + cA) * 2,     aSrc + k0);
        cp16(aS + (rA * GA_PITCH + cA + 8) * 2, aSrc + k0 + 8);
        const __half* bG = bSrc + (size_t)k0 * LDW;
        cp16(bS + (rB * GB_PITCH + cB) * 2,        bG);
        cp16(bS + ((rB + 8) * GB_PITCH + cB) * 2,  bG + (size_t)8 * LDW);
        cp16(bS + ((rB + 16) * GB_PITCH + cB) * 2, bG + (size_t)16 * LDW);
        cp16(bS + ((rB + 24) * GB_PITCH + cB) * 2, bG + (size_t)24 * LDW);
    };

    // fragment bases
    const uint32_t a_frag = sbase + ((lane & 15) * GA_PITCH + (lane >> 4) * 8) * 2;
    const uint32_t b_frag = sbase + GB_OFF + ((lane & 15) * GB_PITCH + wn * 32 + (lane >> 4) * 8) * 2;

    float acc[4][4][4] = {};

    fill(0); cp_commit();
    fill(1); cp_commit();

    for (int it = 0; it < G_NIT; ++it) {
        if (it == G_NIT - 1) cp_wait0(); else cp_wait1();
        __syncthreads();
        if (it + 2 < G_NIT) { fill(it + 2); cp_commit(); }

        const int s = it % 3;
        const uint32_t aS = a_frag + s * GA_STG;
        const uint32_t bS = b_frag + s * GB_STG;
        #pragma unroll
        for (int kk = 0; kk < 2; ++kk) {
            uint32_t aF[4][4];
            #pragma unroll
            for (int mf = 0; mf < 4; ++mf)
                ldsm_x4(aF[mf], aS + (mf * 16 * GA_PITCH + kk * 16) * 2);
            #pragma unroll
            for (int ng = 0; ng < 2; ++ng) {
                uint32_t bF[4];
                ldsm_x4t(bF, bS + (kk * 16 * GB_PITCH + ng * 16) * 2);
                #pragma unroll
                for (int s2 = 0; s2 < 2; ++s2) {
                    const int nf = ng * 2 + s2;
                    #pragma unroll
                    for (int mf = 0; mf < 4; ++mf)
                        mma16h(acc[mf][nf], aF[mf], &bF[s2 * 2]);
                }
            }
        }
    }

    // Epilogue
    if constexpr (QKV) {
        const int wsel = blockIdx.x >> 3;
        const int nl0 = (blockIdx.x & 7) * 128;
        __half* outp = wsel == 0 ? g_q : wsel == 1 ? g_k : g_v;
        const float* bp = wsel == 0 ? bias0 : wsel == 1 ? bias1 : bias2;
        const float scale = wsel == 0 ? qscale : 1.0f;
        #pragma unroll
        for (int nf = 0; nf < 4; ++nf) {
            const int ncol = nl0 + wn * 32 + nf * 8 + 2 * qd;
            const float bx = bp[ncol], by = bp[ncol + 1];
            const int h = ncol >> 6, d = ncol & 63;
            #pragma unroll
            for (int mf = 0; mf < 4; ++mf) {
                const int r = m0 + mf * 16 + rq;
                __half2 p0 = __floats2half2_rn((acc[mf][nf][0] + bx) * scale,
                                               (acc[mf][nf][1] + by) * scale);
                __half2 p1 = __floats2half2_rn((acc[mf][nf][2] + bx) * scale,
                                               (acc[mf][nf][3] + by) * scale);
                const int bb0 = r >> 11, ss0 = r & 2047;
                const int bb1 = (r + 8) >> 11, ss1 = (r + 8) & 2047;
                *(__half2*)(outp + (((size_t)(bb0 * Hc + h) * Sc + ss0) * DHc + d)) = p0;
                *(__half2*)(outp + (((size_t)(bb1 * Hc + h) * Sc + ss1) * DHc + d)) = p1;
            }
        }
    } else {
        #pragma unroll
        for (int nf = 0; nf < 4; ++nf) {
            const int col = n0 + wn * 32 + nf * 8 + 2 * qd;
            const float bx = bias0[col], by = bias0[col + 1];
            #pragma unroll
            for (int mf = 0; mf < 4; ++mf) {
                const int r = m0 + mf * 16 + rq;
                *(float2*)(outF + (size_t)r * Dc + col) =
                    make_float2(acc[mf][nf][0] + bx, acc[mf][nf][1] + by);
                *(float2*)(outF + (size_t)(r + 8) * Dc + col) =
                    make_float2(acc[mf][nf][2] + bx, acc[mf][nf][3] + by);
            }
        }
    }
}

// ---------------------------------------------------------------------------
// FP16 flash attention: MAX-FREE softmax, R14 pipeline (3-stage, wait1,
// one tile per sync), li accumulated in REGISTERS (no ones-column mma).
//   Grid (S/128, B*H), 256 thr = 8 warps x 16 q-rows. Key tile 64.
// ---------------------------------------------------------------------------
constexpr int F_K_OFF = 128 * 72;                 // halves: after Q
constexpr int F_V_OFF = F_K_OFF + 3 * 64 * 72;
constexpr int F_STG   = 64 * 72;                  // halves per stage
constexpr int FLASH_SMEM = (F_V_OFF + 3 * 64 * 72) * 2;   // 73728 bytes
constexpr int F_NT = Sc / 64;                     // 32

__global__ __launch_bounds__(256, 2) void flash_h()
{
    extern __shared__ __half dsm[];
    const int tid = threadIdx.x, lane = tid & 31, wid = tid >> 5;
    const int qt = blockIdx.x, bh = blockIdx.y;
    const __half* Q = g_q + (size_t)bh * Sc * DHc;
    const __half* K = g_k + (size_t)bh * Sc * DHc;
    const __half* V = g_v + (size_t)bh * Sc * DHc;
    const int rq = lane >> 2, qd = lane & 3;

    const uint32_t base = (uint32_t)__cvta_generic_to_shared(dsm);
    const uint32_t k_base = base + F_K_OFF * 2;
    const uint32_t v_base = base + F_V_OFF * 2;

    // Q tile (128 x 64 halves)
    __half (*Qs)[72] = (__half(*)[72])dsm;
    #pragma unroll
    for (int j = 0; j < 4; ++j) {
        const int i = tid + j * 256;
        const int r = i >> 3, c = (i & 7) * 8;
        *(uint4*)&Qs[r][c] = *(const uint4*)(Q + (size_t)(qt * 128 + r) * DHc + c);
    }

    // cp.async K/V mapping (2 x 16B per array per thread)
    const int rKV = tid >> 3, cKV = (tid & 7) * 8;
    auto fillKV = [&](int t) {
        const uint32_t so = (uint32_t)(t % 3) * F_STG * 2;
        const size_t go = (size_t)t * 64 * DHc;
        cp16(k_base + so + (rKV * 72 + cKV) * 2,        K + go + (size_t)rKV * DHc + cKV);
        cp16(k_base + so + ((rKV + 32) * 72 + cKV) * 2, K + go + (size_t)(rKV + 32) * DHc + cKV);
        cp16(v_base + so + (rKV * 72 + cKV) * 2,        V + go + (size_t)rKV * DHc + cKV);
        cp16(v_base + so + ((rKV + 32) * 72 + cKV) * 2, V + go + (size_t)(rKV + 32) * DHc + cKV);
    };

    fillKV(0); cp_commit();
    fillKV(1); cp_commit();
    __syncthreads();    // Q visible

    // Q fragments in registers for the whole loop
    uint32_t aQ[4][4];
    {
        const uint32_t qa = base + ((wid * 16 + (lane & 15)) * 72 + (lane >> 4) * 8) * 2;
        #pragma unroll
        for (int kk = 0; kk < 4; ++kk)
            ldsm_x4(aQ[kk], qa + kk * 16 * 2);
    }

    float accO[8][4] = {};
    float li[2] = {0.0f, 0.0f};

    const uint32_t k_frag = k_base + (((lane >> 4) * 8 + (lane & 7)) * 72 + ((lane >> 3) & 1) * 8) * 2;
    const uint32_t v_frag = v_base + ((lane & 15) * 72 + (lane >> 4) * 8) * 2;

    for (int t = 0; t < F_NT; ++t) {
        if (t == F_NT - 1) cp_wait0(); else cp_wait1();
        __syncthreads();
        if (t + 2 < F_NT) { fillKV(t + 2); cp_commit(); }

        const uint32_t so = (uint32_t)(t % 3) * F_STG * 2;

        // S = Q K^T  (log2-unit scores: Q pre-scaled by log2e/8)
        float accS[8][4] = {};
        #pragma unroll
        for (int kk = 0; kk < 4; ++kk) {
            #pragma unroll
            for (int ng = 0; ng < 4; ++ng) {
                uint32_t bK[4];
                ldsm_x4(bK, k_frag + so + (ng * 16 * 72 + kk * 16) * 2);
                mma16h(accS[2 * ng],     aQ[kk], &bK[0]);
                mma16h(accS[2 * ng + 1], aQ[kk], &bK[2]);
            }
        }

        // Max-free softmax: P = exp2(S) straight into mma A-fragments
        uint32_t aP[4][4];
        #pragma unroll
        for (int nf = 0; nf < 8; ++nf) {
            aP[nf >> 1][((nf & 1) << 1) | 0] = exp2_f16x2(accS[nf][0], accS[nf][1]);
            aP[nf >> 1][((nf & 1) << 1) | 1] = exp2_f16x2(accS[nf][2], accS[nf][3]);
        }

        // li += row partials (fp32 on idle fma pipe; quad-reduce at epilogue)
        #pragma unroll
        for (int h = 0; h < 2; ++h) {
            float s = 0.0f;
            #pragma unroll
            for (int nf = 0; nf < 8; ++nf) {
                const float2 f = __half22float2(
                    *(const __half2*)&aP[nf >> 1][((nf & 1) << 1) | h]);
                s += f.x + f.y;
            }
            li[h] += s;
        }

        // O += P @ V
        #pragma unroll
        for (int kk = 0; kk < 4; ++kk) {
            #pragma unroll
            for (int dg = 0; dg < 4; ++dg) {
                uint32_t bV[4];
                ldsm_x4t(bV, v_frag + so + (kk * 16 * 72 + dg * 16) * 2);
                mma16h(accO[2 * dg],     aP[kk], &bV[0]);
                mma16h(accO[2 * dg + 1], aP[kk], &bV[2]);
            }
        }
    }

    // Epilogue: quad-reduce li, normalize, write ctx [B,S,D]
    #pragma unroll
    for (int h = 0; h < 2; ++h) {
        li[h] += __shfl_xor_sync(0xffffffffu, li[h], 1);
        li[h] += __shfl_xor_sync(0xffffffffu, li[h], 2);
    }
    const float inv0 = 1.0f / li[0];
    const float inv1 = 1.0f / li[1];

    const int bb = bh >> 4, hh = bh & 15;
    const int row = wid * 16 + rq;
    #pragma unroll
    for (int h = 0; h < 2; ++h) {
        const int s_idx = qt * 128 + row + 8 * h;
        const float inv = h ? inv1 : inv0;
        #pragma unroll
        for (int nf = 0; nf < 8; ++nf) {
            __half2 o = __floats2half2_rn(accO[nf][2 * h] * inv,
                                          accO[nf][2 * h + 1] * inv);
            *(__half2*)(g_ctx + ((size_t)(bb * Sc + s_idx) * Dc + hh * DHc + nf * 8 + 2 * qd)) = o;
        }
    }
}

// ---------------------------------------------------------------------------
extern "C" void kernel_launch(void* const* d_in, const int* in_sizes, int n_in,
                              void* d_out, int out_size)
{
    const float* x  = (const float*)d_in[0];
    const float* wq = (const float*)d_in[1];
    const float* bq = (const float*)d_in[2];
    const float* wk = (const float*)d_in[3];
    const float* bk = (const float*)d_in[4];
    const float* wv = (const float*)d_in[5];
    const float* bv = (const float*)d_in[6];
    const float* wo = (const float*)d_in[7];
    const float* bo = (const float*)d_in[8];
    float* out = (float*)d_out;

    static bool attr_set = false;
    if (!attr_set) {
        cudaFuncSetAttribute(flash_h, cudaFuncAttributeMaxDynamicSharedMemorySize,
                             FLASH_SMEM);
        cudaFuncSetAttribute(gemm_cp<true>, cudaFuncAttributeMaxDynamicSharedMemorySize,
                             G_SMEM);
        cudaFuncSetAttribute(gemm_cp<false>, cudaFuncAttributeMaxDynamicSharedMemorySize,
                             G_SMEM);
        attr_set = true;
    }

    const float qscale = 1.4426950408889634f / 8.0f;   // log2(e)/sqrt(Dh)

    // fp32 -> fp16 conversion pre-pass (fused single launch)
    cvt_all<<<5120, 256>>>(x, wq, wk, wv, wo);

    // Fused QKV projection (N = 3072), 64x128 tiles, 128 thr, 4 CTAs/SM
    gemm_cp<true><<<dim3(3 * Dc / 128, Mc / 64), 128, G_SMEM>>>(bq, bk, bv, nullptr, qscale);

    // Attention (max-free softmax, li in registers)
    flash_h<<<dim3(Sc / 128, Bc * Hc), 256, FLASH_SMEM>>>();

    // Output projection
    gemm_cp<false><<<dim3(Dc / 128, Mc / 64), 128, G_SMEM>>>(bo, nullptr, nullptr, out, 1.0f);
}

// round 17
// speedup vs baseline: 1.0292x; 1.0281x over previous
#include <cuda_runtime.h>
#include <cuda_fp16.h>
#include <math.h>
#include <stdint.h>

// Problem constants
constexpr int Bc = 4;
constexpr int Sc = 2048;
constexpr int Dc = 1024;
constexpr int Hc = 16;
constexpr int DHc = 64;
constexpr int Mc = Bc * Sc;    // 8192

// Scratch (device globals — no allocation allowed)
__device__ __align__(16) __half g_q[(size_t)Bc * Hc * Sc * DHc];
__device__ __align__(16) __half g_k[(size_t)Bc * Hc * Sc * DHc];
__device__ __align__(16) __half g_v[(size_t)Bc * Hc * Sc * DHc];
__device__ __align__(16) __half g_ctx[(size_t)Mc * Dc];
__device__ __align__(16) __half g_xh[(size_t)Mc * Dc];          // x in fp16
__device__ __align__(16) __half g_wcat[(size_t)Dc * 3 * Dc];    // [k][3072] = Wq|Wk|Wv
__device__ __align__(16) __half g_woh[(size_t)Dc * Dc];         // Wo fp16

// ---- primitives ------------------------------------------------------------
__device__ __forceinline__ void mma16h(float* c, const uint32_t* a, const uint32_t* b) {
    asm volatile(
        "mma.sync.aligned.m16n8k16.row.col.f32.f16.f16.f32 "
        "{%0,%1,%2,%3}, {%4,%5,%6,%7}, {%8,%9}, {%0,%1,%2,%3};\n"
        : "+f"(c[0]), "+f"(c[1]), "+f"(c[2]), "+f"(c[3])
        : "r"(a[0]), "r"(a[1]), "r"(a[2]), "r"(a[3]), "r"(b[0]), "r"(b[1]));
}
__device__ __forceinline__ void ldsm_x4(uint32_t* r, uint32_t addr) {
    asm volatile("ldmatrix.sync.aligned.m8n8.x4.shared.b16 {%0,%1,%2,%3}, [%4];"
                 : "=r"(r[0]), "=r"(r[1]), "=r"(r[2]), "=r"(r[3]) : "r"(addr));
}
__device__ __forceinline__ void ldsm_x4t(uint32_t* r, uint32_t addr) {
    asm volatile("ldmatrix.sync.aligned.m8n8.x4.trans.shared.b16 {%0,%1,%2,%3}, [%4];"
                 : "=r"(r[0]), "=r"(r[1]), "=r"(r[2]), "=r"(r[3]) : "r"(addr));
}
__device__ __forceinline__ void ldsm_x2t(uint32_t* r, uint32_t addr) {
    asm volatile("ldmatrix.sync.aligned.m8n8.x2.trans.shared.b16 {%0,%1}, [%2];"
                 : "=r"(r[0]), "=r"(r[1]) : "r"(addr));
}
__device__ __forceinline__ uint32_t exp2_f16x2(float lo, float hi) {
    uint32_t u;
    asm("{\n\t.reg .b32 t;\n\t"
        "cvt.rn.f16x2.f32 t, %1, %2;\n\t"
        "ex2.approx.f16x2 %0, t;\n\t}"
        : "=r"(u) : "f"(hi), "f"(lo));
    return u;
}
__device__ __forceinline__ void cp16(uint32_t saddr, const void* g) {
    asm volatile("cp.async.cg.shared.global [%0], [%1], 16;" :: "r"(saddr), "l"(g));
}
__device__ __forceinline__ void cp_commit() { asm volatile("cp.async.commit_group;" ::: "memory"); }
__device__ __forceinline__ void cp_wait1()  { asm volatile("cp.async.wait_group 1;" ::: "memory"); }
__device__ __forceinline__ void cp_wait0()  { asm volatile("cp.async.wait_group 0;" ::: "memory"); }

// ---------------------------------------------------------------------------
// fp32 -> fp16 conversion pre-pass (single fused kernel: x + all weights)
// ---------------------------------------------------------------------------
__global__ __launch_bounds__(256) void cvt_all(
    const float* __restrict__ x,
    const float* __restrict__ wq, const float* __restrict__ wk,
    const float* __restrict__ wv, const float* __restrict__ wo)
{
    if (blockIdx.x < 4096) {
        const size_t i = ((size_t)blockIdx.x * 256 + threadIdx.x) * 8;
        const float4 f0 = *(const float4*)(x + i);
        const float4 f1 = *(const float4*)(x + i + 4);
        __half2 h0 = __floats2half2_rn(f0.x, f0.y), h1 = __floats2half2_rn(f0.z, f0.w);
        __half2 h2 = __floats2half2_rn(f1.x, f1.y), h3 = __floats2half2_rn(f1.z, f1.w);
        uint4 p = { *(uint32_t*)&h0, *(uint32_t*)&h1, *(uint32_t*)&h2, *(uint32_t*)&h3 };
        *(uint4*)(g_xh + i) = p;
    } else {
        const size_t i = ((size_t)(blockIdx.x - 4096) * 256 + threadIdx.x) * 4;
        const int k = (int)(i >> 10), n = (int)(i & 1023);
        const float4 q4 = *(const float4*)(wq + i);
        const float4 k4 = *(const float4*)(wk + i);
        const float4 v4 = *(const float4*)(wv + i);
        const float4 o4 = *(const float4*)(wo + i);
        __half2 a, b;
        a = __floats2half2_rn(q4.x, q4.y); b = __floats2half2_rn(q4.z, q4.w);
        { uint2 p = { *(uint32_t*)&a, *(uint32_t*)&b }; *(uint2*)(g_wcat + (size_t)k * 3072 + n) = p; }
        a = __floats2half2_rn(k4.x, k4.y); b = __floats2half2_rn(k4.z, k4.w);
        { uint2 p = { *(uint32_t*)&a, *(uint32_t*)&b }; *(uint2*)(g_wcat + (size_t)k * 3072 + 1024 + n) = p; }
        a = __floats2half2_rn(v4.x, v4.y); b = __floats2half2_rn(v4.z, v4.w);
        { uint2 p = { *(uint32_t*)&a, *(uint32_t*)&b }; *(uint2*)(g_wcat + (size_t)k * 3072 + 2048 + n) = p; }
        a = __floats2half2_rn(o4.x, o4.y); b = __floats2half2_rn(o4.z, o4.w);
        { uint2 p = { *(uint32_t*)&a, *(uint32_t*)&b }; *(uint2*)(g_woh + i) = p; }
    }
}

// ---------------------------------------------------------------------------
// FP16 GEMM (R14 proven config, verbatim): tile 64x128, BK=32, 128 threads
//   (4 warps, warp tile 64x32), 3-stage cp.async, one sync per iter, 4 CTAs/SM.
// ---------------------------------------------------------------------------
constexpr int GA_PITCH = 40;                       // halves (80 B)
constexpr int GB_PITCH = 136;                      // halves (272 B)
constexpr uint32_t GA_STG = 64 * GA_PITCH * 2;     // 5120 B
constexpr uint32_t GB_STG = 32 * GB_PITCH * 2;     // 8704 B
constexpr uint32_t GB_OFF = 3 * GA_STG;            // 15360
constexpr int G_SMEM = (int)(GB_OFF + 3 * GB_STG); // 41472 B -> 4 CTAs = 166 KB
constexpr int G_NIT = Dc / 32;                     // 32

template<bool QKV>
__global__ __launch_bounds__(128, 4) void gemm_cp(
    const float* __restrict__ bias0,
    const float* __restrict__ bias1,
    const float* __restrict__ bias2,
    float* __restrict__ outF,
    float qscale)
{
    extern __shared__ char gsm[];
    const uint32_t sbase = (uint32_t)__cvta_generic_to_shared(gsm);
    constexpr int LDW = QKV ? 3072 : 1024;
    const __half* A = QKV ? g_xh : g_ctx;
    const __half* W = QKV ? g_wcat : g_woh;

    const int tid = threadIdx.x, lane = tid & 31, wid = tid >> 5;
    const int wn = wid;                         // 4 warps across N
    const int m0 = blockIdx.y * 64;
    const int n0 = blockIdx.x * 128;
    const int rq = lane >> 2, qd = lane & 3;

    const int rA = tid >> 1, cA = (tid & 1) * 16;       // rows 0..63
    const int rB = tid >> 4, cB = (tid & 15) * 8;       // rows 0..7 (+8,+16,+24)
    const __half* aSrc = A + (size_t)(m0 + rA) * Dc + cA;
    const __half* bSrc = W + (size_t)rB * LDW + n0 + cB;

    auto fill = [&](int j) {
        const int s = j % 3;
        const int k0 = j * 32;
        const uint32_t aS = sbase + s * GA_STG;
        const uint32_t bS = sbase + GB_OFF + s * GB_STG;
        cp16(aS + (rA * GA_PITCH + cA) * 2,     aSrc + k0);
        cp16(aS + (rA * GA_PITCH + cA + 8) * 2, aSrc + k0 + 8);
        const __half* bG = bSrc + (size_t)k0 * LDW;
        cp16(bS + (rB * GB_PITCH + cB) * 2,        bG);
        cp16(bS + ((rB + 8) * GB_PITCH + cB) * 2,  bG + (size_t)8 * LDW);
        cp16(bS + ((rB + 16) * GB_PITCH + cB) * 2, bG + (size_t)16 * LDW);
        cp16(bS + ((rB + 24) * GB_PITCH + cB) * 2, bG + (size_t)24 * LDW);
    };

    const uint32_t a_frag = sbase + ((lane & 15) * GA_PITCH + (lane >> 4) * 8) * 2;
    const uint32_t b_frag = sbase + GB_OFF + ((lane & 15) * GB_PITCH + wn * 32 + (lane >> 4) * 8) * 2;

    float acc[4][4][4] = {};

    fill(0); cp_commit();
    fill(1); cp_commit();

    for (int it = 0; it < G_NIT; ++it) {
        if (it == G_NIT - 1) cp_wait0(); else cp_wait1();
        __syncthreads();
        if (it + 2 < G_NIT) { fill(it + 2); cp_commit(); }

        const int s = it % 3;
        const uint32_t aS = a_frag + s * GA_STG;
        const uint32_t bS = b_frag + s * GB_STG;
        #pragma unroll
        for (int kk = 0; kk < 2; ++kk) {
            uint32_t aF[4][4];
            #pragma unroll
            for (int mf = 0; mf < 4; ++mf)
                ldsm_x4(aF[mf], aS + (mf * 16 * GA_PITCH + kk * 16) * 2);
            #pragma unroll
            for (int ng = 0; ng < 2; ++ng) {
                uint32_t bF[4];
                ldsm_x4t(bF, bS + (kk * 16 * GB_PITCH + ng * 16) * 2);
                #pragma unroll
                for (int s2 = 0; s2 < 2; ++s2) {
                    const int nf = ng * 2 + s2;
                    #pragma unroll
                    for (int mf = 0; mf < 4; ++mf)
                        mma16h(acc[mf][nf], aF[mf], &bF[s2 * 2]);
                }
            }
        }
    }

    // Epilogue
    if constexpr (QKV) {
        const int wsel = blockIdx.x >> 3;
        const int nl0 = (blockIdx.x & 7) * 128;
        __half* outp = wsel == 0 ? g_q : wsel == 1 ? g_k : g_v;
        const float* bp = wsel == 0 ? bias0 : wsel == 1 ? bias1 : bias2;
        const float scale = wsel == 0 ? qscale : 1.0f;
        #pragma unroll
        for (int nf = 0; nf < 4; ++nf) {
            const int ncol = nl0 + wn * 32 + nf * 8 + 2 * qd;
            const float bx = bp[ncol], by = bp[ncol + 1];
            const int h = ncol >> 6, d = ncol & 63;
            #pragma unroll
            for (int mf = 0; mf < 4; ++mf) {
                const int r = m0 + mf * 16 + rq;
                __half2 p0 = __floats2half2_rn((acc[mf][nf][0] + bx) * scale,
                                               (acc[mf][nf][1] + by) * scale);
                __half2 p1 = __floats2half2_rn((acc[mf][nf][2] + bx) * scale,
                                               (acc[mf][nf][3] + by) * scale);
                const int bb0 = r >> 11, ss0 = r & 2047;
                const int bb1 = (r + 8) >> 11, ss1 = (r + 8) & 2047;
                *(__half2*)(outp + (((size_t)(bb0 * Hc + h) * Sc + ss0) * DHc + d)) = p0;
                *(__half2*)(outp + (((size_t)(bb1 * Hc + h) * Sc + ss1) * DHc + d)) = p1;
            }
        }
    } else {
        #pragma unroll
        for (int nf = 0; nf < 4; ++nf) {
            const int col = n0 + wn * 32 + nf * 8 + 2 * qd;
            const float bx = bias0[col], by = bias0[col + 1];
            #pragma unroll
            for (int mf = 0; mf < 4; ++mf) {
                const int r = m0 + mf * 16 + rq;
                *(float2*)(outF + (size_t)r * Dc + col) =
                    make_float2(acc[mf][nf][0] + bx, acc[mf][nf][1] + by);
                *(float2*)(outF + (size_t)(r + 8) * Dc + col) =
                    make_float2(acc[mf][nf][2] + bx, acc[mf][nf][3] + by);
            }
        }
    }
}

// ---------------------------------------------------------------------------
// FP16 flash attention: MAX-FREE softmax, ones-column li (proven),
// PAIR pipeline: 4 stages, 2 tiles processed per wait0/sync (16 syncs).
//   Grid (S/128, B*H), 256 thr = 8 warps x 16 q-rows. Key tile 64.
// ---------------------------------------------------------------------------
constexpr int F_NSTG = 4;
constexpr int F_STG  = 64 * 72;                   // halves per stage
constexpr int F_K_OFF = 128 * 72;                 // after Q
constexpr int F_V_OFF = F_K_OFF + F_NSTG * F_STG;
constexpr int FLASH_SMEM = (F_V_OFF + F_NSTG * F_STG) * 2;   // 92160 B -> 2 CTAs
constexpr int F_NT = Sc / 64;                     // 32

__global__ __launch_bounds__(256, 2) void flash_h()
{
    extern __shared__ __half dsm[];
    const int tid = threadIdx.x, lane = tid & 31, wid = tid >> 5;
    const int qt = blockIdx.x, bh = blockIdx.y;
    const __half* Q = g_q + (size_t)bh * Sc * DHc;
    const __half* K = g_k + (size_t)bh * Sc * DHc;
    const __half* V = g_v + (size_t)bh * Sc * DHc;
    const int rq = lane >> 2, qd = lane & 3;

    const uint32_t base = (uint32_t)__cvta_generic_to_shared(dsm);
    const uint32_t k_base = base + F_K_OFF * 2;
    const uint32_t v_base = base + F_V_OFF * 2;

    // Q tile (128 x 64 halves)
    __half (*Qs)[72] = (__half(*)[72])dsm;
    #pragma unroll
    for (int j = 0; j < 4; ++j) {
        const int i = tid + j * 256;
        const int r = i >> 3, c = (i & 7) * 8;
        *(uint4*)&Qs[r][c] = *(const uint4*)(Q + (size_t)(qt * 128 + r) * DHc + c);
    }
    // ones-columns of all 4 V stages (cp.async never touches cols 64-71)
    {
        __half* Vb = dsm + F_V_OFF;
        const int s = tid >> 6, r = tid & 63;     // 256 thr = 4 stages x 64 rows
        const uint4 onesv = { 0x00003C00u, 0u, 0u, 0u };
        *(uint4*)&Vb[(size_t)s * F_STG + r * 72 + 64] = onesv;
    }

    // cp.async K/V mapping (2 x 16B per array per thread)
    const int rKV = tid >> 3, cKV = (tid & 7) * 8;
    auto fillKV = [&](int t) {
        const uint32_t so = (uint32_t)(t & (F_NSTG - 1)) * F_STG * 2;
        const size_t go = (size_t)t * 64 * DHc;
        cp16(k_base + so + (rKV * 72 + cKV) * 2,        K + go + (size_t)rKV * DHc + cKV);
        cp16(k_base + so + ((rKV + 32) * 72 + cKV) * 2, K + go + (size_t)(rKV + 32) * DHc + cKV);
        cp16(v_base + so + (rKV * 72 + cKV) * 2,        V + go + (size_t)rKV * DHc + cKV);
        cp16(v_base + so + ((rKV + 32) * 72 + cKV) * 2, V + go + (size_t)(rKV + 32) * DHc + cKV);
    };

    fillKV(0); fillKV(1); cp_commit();
    __syncthreads();    // Q and ones-columns visible

    // Q fragments in registers for the whole loop
    uint32_t aQ[4][4];
    {
        const uint32_t qa = base + ((wid * 16 + (lane & 15)) * 72 + (lane >> 4) * 8) * 2;
        #pragma unroll
        for (int kk = 0; kk < 4; ++kk)
            ldsm_x4(aQ[kk], qa + kk * 16 * 2);
    }

    float accO[8][4] = {};
    float accO8[4] = {};

    const uint32_t k_frag = k_base + (((lane >> 4) * 8 + (lane & 7)) * 72 + ((lane >> 3) & 1) * 8) * 2;
    const uint32_t v_frag = v_base + ((lane & 15) * 72 + (lane >> 4) * 8) * 2;
    const uint32_t v1_frag = v_base + ((lane & 15) * 72 + 64) * 2;

    auto process = [&](int t) {
        const uint32_t so = (uint32_t)(t & (F_NSTG - 1)) * F_STG * 2;

        // S = Q K^T  (log2-unit scores: Q pre-scaled by log2e/8)
        float accS[8][4] = {};
        #pragma unroll
        for (int kk = 0; kk < 4; ++kk) {
            #pragma unroll
            for (int ng = 0; ng < 4; ++ng) {
                uint32_t bK[4];
                ldsm_x4(bK, k_frag + so + (ng * 16 * 72 + kk * 16) * 2);
                mma16h(accS[2 * ng],     aQ[kk], &bK[0]);
                mma16h(accS[2 * ng + 1], aQ[kk], &bK[2]);
            }
        }

        // Max-free softmax: P = exp2(S) straight into mma A-fragments
        uint32_t aP[4][4];
        #pragma unroll
        for (int nf = 0; nf < 8; ++nf) {
            aP[nf >> 1][((nf & 1) << 1) | 0] = exp2_f16x2(accS[nf][0], accS[nf][1]);
            aP[nf >> 1][((nf & 1) << 1) | 1] = exp2_f16x2(accS[nf][2], accS[nf][3]);
        }

        // O += P @ V  (+ ones-column -> row sums into accO8)
        #pragma unroll
        for (int kk = 0; kk < 4; ++kk) {
            #pragma unroll
            for (int dg = 0; dg < 4; ++dg) {
                uint32_t bV[4];
                ldsm_x4t(bV, v_frag + so + (kk * 16 * 72 + dg * 16) * 2);
                mma16h(accO[2 * dg],     aP[kk], &bV[0]);
                mma16h(accO[2 * dg + 1], aP[kk], &bV[2]);
            }
            uint32_t b1[2];
            ldsm_x2t(b1, v1_frag + so + kk * 16 * 72 * 2);
            mma16h(accO8, aP[kk], b1);
        }
    };

    for (int t = 0; t < F_NT; t += 2) {
        cp_wait0();
        __syncthreads();
        if (t + 2 < F_NT) { fillKV(t + 2); fillKV(t + 3); cp_commit(); }
        process(t);
        process(t + 1);
    }

    // Epilogue: li from ones-column (col 64 -> qd==0 threads), broadcast in quad
    const float li0 = __shfl_sync(0xffffffffu, accO8[0], lane & ~3);
    const float li1 = __shfl_sync(0xffffffffu, accO8[2], lane & ~3);
    const float inv0 = 1.0f / li0;
    const float inv1 = 1.0f / li1;

    const int bb = bh >> 4, hh = bh & 15;
    const int row = wid * 16 + rq;
    #pragma unroll
    for (int h = 0; h < 2; ++h) {
        const int s_idx = qt * 128 + row + 8 * h;
        const float inv = h ? inv1 : inv0;
        #pragma unroll
        for (int nf = 0; nf < 8; ++nf) {
            __half2 o = __floats2half2_rn(accO[nf][2 * h] * inv,
                                          accO[nf][2 * h + 1] * inv);
            *(__half2*)(g_ctx + ((size_t)(bb * Sc + s_idx) * Dc + hh * DHc + nf * 8 + 2 * qd)) = o;
        }
    }
}

// ---------------------------------------------------------------------------
extern "C" void kernel_launch(void* const* d_in, const int* in_sizes, int n_in,
                              void* d_out, int out_size)
{
    const float* x  = (const float*)d_in[0];
    const float* wq = (const float*)d_in[1];
    const float* bq = (const float*)d_in[2];
    const float* wk = (const float*)d_in[3];
    const float* bk = (const float*)d_in[4];
    const float* wv = (const float*)d_in[5];
    const float* bv = (const float*)d_in[6];
    const float* wo = (const float*)d_in[7];
    const float* bo = (const float*)d_in[8];
    float* out = (float*)d_out;

    static bool attr_set = false;
    if (!attr_set) {
        cudaFuncSetAttribute(flash_h, cudaFuncAttributeMaxDynamicSharedMemorySize,
                             FLASH_SMEM);
        cudaFuncSetAttribute(gemm_cp<true>, cudaFuncAttributeMaxDynamicSharedMemorySize,
                             G_SMEM);
        cudaFuncSetAttribute(gemm_cp<false>, cudaFuncAttributeMaxDynamicSharedMemorySize,
                             G_SMEM);
        attr_set = true;
    }

    const float qscale = 1.4426950408889634f / 8.0f;   // log2(e)/sqrt(Dh)

    // fp32 -> fp16 conversion pre-pass (fused single launch)
    cvt_all<<<5120, 256>>>(x, wq, wk, wv, wo);

    // Fused QKV projection (N = 3072), 64x128 tiles, 128 thr, 4 CTAs/SM
    gemm_cp<true><<<dim3(3 * Dc / 128, Mc / 64), 128, G_SMEM>>>(bq, bk, bv, nullptr, qscale);

    // Attention (max-free softmax, ones-column li, pair pipeline)
    flash_h<<<dim3(Sc / 128, Bc * Hc), 256, FLASH_SMEM>>>();

    // Output projection
    gemm_cp<false><<<dim3(Dc / 128, Mc / 64), 128, G_SMEM>>>(bo, nullptr, nullptr, out, 1.0f);
}